// round 10
// baseline (speedup 1.0000x reference)
#include <cuda_runtime.h>
#include <math.h>
#include <stdint.h>

#define BB 4
#define LL 4096
#define TT (BB*LL)
#define DM 1024
#define HH 16
#define DH 64
#define MF 128
#define TWO_M 256
#define KV_SPLIT 16
#define LSPLIT (LL/KV_SPLIT)   // 256

#define INV_SQRT_DH 0.125f
#define INV_SQRT_MF 0.08838834764831843f

__device__ float g_q[TT*DM];
__device__ float g_k[TT*DM];
__device__ float g_v[TT*DM];
__device__ float g_att[TT*DM];
__device__ float g_wr[4*DM*DM];
__device__ float g_kvp[(size_t)KV_SPLIT*BB*HH*TWO_M*DH];
__device__ float g_kv[(size_t)BB*HH*TWO_M*DH];

__device__ __forceinline__ float tf32r(float x) {
    uint32_t u;
    asm("cvt.rna.tf32.f32 %0, %1;" : "=r"(u) : "f"(x));
    return __uint_as_float(u);
}

__device__ __forceinline__ void mma_tf32(float* d, const uint32_t* a, const uint32_t* b) {
    asm volatile(
        "mma.sync.aligned.m16n8k8.row.col.f32.tf32.tf32.f32 "
        "{%0,%1,%2,%3}, {%4,%5,%6,%7}, {%8,%9}, {%0,%1,%2,%3};\n"
        : "+f"(d[0]), "+f"(d[1]), "+f"(d[2]), "+f"(d[3])
        : "r"(a[0]), "r"(a[1]), "r"(a[2]), "r"(a[3]), "r"(b[0]), "r"(b[1]));
}

__device__ __forceinline__ uint32_t smaddr(const void* p) {
    return (uint32_t)__cvta_generic_to_shared(p);
}

__device__ __forceinline__ void ldsm4(uint32_t* r, uint32_t a) {
    asm volatile("ldmatrix.sync.aligned.m8n8.x4.shared.b16 {%0,%1,%2,%3}, [%4];"
                 : "=r"(r[0]), "=r"(r[1]), "=r"(r[2]), "=r"(r[3]) : "r"(a));
}

#define AOFF(lane, STR) (((((lane) >> 3) & 1) * 8 + ((lane) & 7)) * (STR) + ((lane) >> 4) * 4)
#define BOFF(lane, STR) ((((lane) >> 4) * 8 + ((lane) & 7)) * (STR) + (((lane) >> 3) & 1) * 4)

// ---------------------------------------------------------------------------
__global__ void round_w(const float4* __restrict__ wq, const float4* __restrict__ wk,
                        const float4* __restrict__ wv, const float4* __restrict__ wo,
                        float4* __restrict__ dst)
{
    const int WN4 = DM * DM / 4;
    int i = blockIdx.x * 256 + threadIdx.x;
    if (i >= 4 * WN4) return;
    int sel = i / WN4, off = i - sel * WN4;
    const float4* src = (sel == 0) ? wq : (sel == 1) ? wk : (sel == 2) ? wv : wo;
    float4 v = src[off];
    v.x = tf32r(v.x); v.y = tf32r(v.y); v.z = tf32r(v.z); v.w = tf32r(v.w);
    dst[i] = v;
}

// ---------------------------------------------------------------------------
// GEMM body: C[128,128 tile] = A[M,1024] * W[N,1024]^T + bias
// cp.async 3-stage pipeline, ldmatrix fragment loads. 256 threads, 2 CTA/SM.
// ---------------------------------------------------------------------------
#define GS 3
#define GSTR 36
#define GSTAGE (128*GSTR)
#define GSMEM (2*GS*GSTAGE*4)

__device__ __forceinline__ void gemm_body(
    const float* __restrict__ A, const float* __restrict__ W,
    const float* __restrict__ bias, float* __restrict__ C)
{
    extern __shared__ float sg[];
    float* As = sg;
    float* Ws = sg + GS * GSTAGE;

    const int tid = threadIdx.x;
    const int bm = blockIdx.y * 128;
    const int bn = blockIdx.x * 128;
    const int warp = tid >> 5, lane = tid & 31;
    const int wm = (warp & 1) * 64;
    const int wn = (warp >> 1) * 32;
    const int g = lane >> 2, c = lane & 3;
    const int aoff = AOFF(lane, GSTR);
    const int boff = BOFF(lane, GSTR);

    float d[4][4][4];
#pragma unroll
    for (int mt = 0; mt < 4; mt++)
#pragma unroll
        for (int nt = 0; nt < 4; nt++)
#pragma unroll
            for (int r = 0; r < 4; r++) d[mt][nt][r] = 0.f;

    auto issue = [&](int st, int k0) {
#pragma unroll
        for (int j = 0; j < 4; j++) {
            int id = tid + j * 256;
            int row = id >> 3, kq = (id & 7) * 4;
            asm volatile("cp.async.cg.shared.global [%0], [%1], 16;\n"
                         :: "r"(smaddr(&As[st * GSTAGE + row * GSTR + kq])),
                            "l"(A + (size_t)(bm + row) * DM + k0 + kq));
            asm volatile("cp.async.cg.shared.global [%0], [%1], 16;\n"
                         :: "r"(smaddr(&Ws[st * GSTAGE + row * GSTR + kq])),
                            "l"(W + (size_t)(bn + row) * DM + k0 + kq));
        }
    };

    issue(0, 0);  asm volatile("cp.async.commit_group;\n");
    issue(1, 32); asm volatile("cp.async.commit_group;\n");

    const int NIT = DM / 32;
    for (int i = 0; i < NIT; i++) {
        asm volatile("cp.async.wait_group 1;\n");
        __syncthreads();
        if (i + 2 < NIT) issue((i + 2) % GS, (i + 2) * 32);
        asm volatile("cp.async.commit_group;\n");

        const float* Ab = As + (i % GS) * GSTAGE;
        const float* Wb = Ws + (i % GS) * GSTAGE;
#pragma unroll
        for (int ks = 0; ks < 4; ks++) {
            const int kb = ks * 8;
            uint32_t a[4][4], bq2[2][4];
#pragma unroll
            for (int mt = 0; mt < 4; mt++)
                ldsm4(a[mt], smaddr(Ab + (wm + mt * 16) * GSTR + kb + aoff));
            ldsm4(bq2[0], smaddr(Wb + wn * GSTR + kb + boff));
            ldsm4(bq2[1], smaddr(Wb + (wn + 16) * GSTR + kb + boff));
#pragma unroll
            for (int mt = 0; mt < 4; mt++)
#pragma unroll
                for (int nt = 0; nt < 4; nt++)
                    mma_tf32(d[mt][nt], a[mt], &bq2[nt >> 1][(nt & 1) * 2]);
        }
    }

#pragma unroll
    for (int nt = 0; nt < 4; nt++) {
        int col = bn + wn + nt * 8 + 2 * c;
        float b0 = bias[col], b1 = bias[col + 1];
#pragma unroll
        for (int mt = 0; mt < 4; mt++) {
            int row = bm + wm + mt * 16 + g;
            *(float2*)(C + (size_t)row * DM + col) =
                make_float2(d[mt][nt][0] + b0, d[mt][nt][1] + b1);
            *(float2*)(C + (size_t)(row + 8) * DM + col) =
                make_float2(d[mt][nt][2] + b0, d[mt][nt][3] + b1);
        }
    }
}

__global__ __launch_bounds__(256, 2) void kv_gemm(
    const float* __restrict__ A, const float* __restrict__ Wr,
    const float* __restrict__ bk, const float* __restrict__ bv,
    float* __restrict__ k, float* __restrict__ v)
{
    int z = blockIdx.z;   // 0 -> K, 1 -> V
    const float* W = Wr + (size_t)(z + 1) * DM * DM;
    const float* bias = (z == 0) ? bk : bv;
    float* C = (z == 0) ? k : v;
    gemm_body(A, W, bias, C);
}

__global__ __launch_bounds__(256, 2) void gemm_one(
    const float* __restrict__ A, const float* __restrict__ W,
    const float* __restrict__ bias, float* __restrict__ C)
{
    gemm_body(A, W, bias, C);
}

// ---------------------------------------------------------------------------
// feat_kv: per (split,h) for batch bsel: kv[256,64] = sum_l k'(l)^T v(l)
// ---------------------------------------------------------------------------
#define FSTR 68
#define FEAT_SMEM ((128*FSTR + 3*64*FSTR + 256*FSTR) * 4)

__global__ __launch_bounds__(512) void feat_kv(
    const float* __restrict__ Kmat, const float* __restrict__ Vmat,
    const float* __restrict__ proj, float* __restrict__ kvp, int bsel)
{
    extern __shared__ float sm[];
    float* projT = sm;
    float* ksh   = projT + 128 * FSTR;
    float* ksl   = ksh   + 64 * FSTR;
    float* vts   = ksl   + 64 * FSTR;
    float* kpt   = vts   + 64 * FSTR;

    const int split = blockIdx.x, h = blockIdx.y, b = bsel;
    const int tid = threadIdx.x;
    const int warp = tid >> 5, lane = tid & 31;
    const int g = lane >> 2, c = lane & 3;
    const int aoff = AOFF(lane, FSTR);
    const int boff = BOFF(lane, FSTR);

    for (int it = tid; it < 2048; it += 512) {
        int d = it >> 5;
        int m4 = (it & 31) * 4;
        float4 pv = *(const float4*)(proj + d * MF + m4);
        projT[(m4 + 0) * FSTR + d] = tf32r(pv.x);
        projT[(m4 + 1) * FSTR + d] = tf32r(pv.y);
        projT[(m4 + 2) * FSTR + d] = tf32r(pv.z);
        projT[(m4 + 3) * FSTR + d] = tf32r(pv.w);
    }

    float kvacc[4][2][4];
#pragma unroll
    for (int mi = 0; mi < 4; mi++)
#pragma unroll
        for (int nj = 0; nj < 2; nj++)
#pragma unroll
            for (int r = 0; r < 4; r++) kvacc[mi][nj][r] = 0.f;

    const int wtokA = (warp & 3) * 16, wmA = (warp >> 2) * 32;
    const int mB0 = (warp & 3) * 64, dB0 = (warp >> 2) * 16;
    const int l0 = split * LSPLIT;

    for (int ch = 0; ch < LSPLIT; ch += 64) {
        __syncthreads();
        for (int it = tid; it < 1024; it += 512) {
            int t = it >> 4;
            int d4 = (it & 15) * 4;
            size_t row = (size_t)(b * LL + l0 + ch + t) * DM + h * DH + d4;
            float4 kvv = *(const float4*)(Kmat + row);
            float hx = tf32r(kvv.x), hy = tf32r(kvv.y), hz = tf32r(kvv.z), hw = tf32r(kvv.w);
            *(float4*)&ksh[t * FSTR + d4] = make_float4(hx, hy, hz, hw);
            *(float4*)&ksl[t * FSTR + d4] = make_float4(
                tf32r(kvv.x - hx), tf32r(kvv.y - hy), tf32r(kvv.z - hz), tf32r(kvv.w - hw));
            float4 vv = *(const float4*)(Vmat + row);
            vts[(d4 + 0) * FSTR + t] = tf32r(vv.x);
            vts[(d4 + 1) * FSTR + t] = tf32r(vv.y);
            vts[(d4 + 2) * FSTR + t] = tf32r(vv.z);
            vts[(d4 + 3) * FSTR + t] = tf32r(vv.w);
        }
        __syncthreads();

        float pacc[4][4];
#pragma unroll
        for (int nj = 0; nj < 4; nj++)
#pragma unroll
            for (int r = 0; r < 4; r++) pacc[nj][r] = 0.f;

#pragma unroll
        for (int ks = 0; ks < 8; ks++) {
            const int kb = ks * 8;
            uint32_t ah[4], al[4], bfr[2][4];
            ldsm4(ah, smaddr(ksh + wtokA * FSTR + kb + aoff));
            ldsm4(al, smaddr(ksl + wtokA * FSTR + kb + aoff));
            ldsm4(bfr[0], smaddr(projT + wmA * FSTR + kb + boff));
            ldsm4(bfr[1], smaddr(projT + (wmA + 16) * FSTR + kb + boff));
#pragma unroll
            for (int nj = 0; nj < 4; nj++) {
                mma_tf32(pacc[nj], ah, &bfr[nj >> 1][(nj & 1) * 2]);
                mma_tf32(pacc[nj], al, &bfr[nj >> 1][(nj & 1) * 2]);
            }
        }

#pragma unroll
        for (int nj = 0; nj < 4; nj++)
#pragma unroll
            for (int r = 0; r < 4; r++) {
                int tok = wtokA + g + (r >> 1) * 8;
                int m = wmA + nj * 8 + 2 * c + (r & 1);
                float p = pacc[nj][r] * INV_SQRT_DH;
                kpt[m * FSTR + tok] = tf32r(__cosf(p) * INV_SQRT_MF);
                kpt[(m + 128) * FSTR + tok] = tf32r(__sinf(p) * INV_SQRT_MF);
            }
        __syncthreads();

#pragma unroll
        for (int ks = 0; ks < 8; ks++) {
            const int kb = ks * 8;
            uint32_t af[4][4], bv2[4];
#pragma unroll
            for (int mi = 0; mi < 4; mi++)
                ldsm4(af[mi], smaddr(kpt + (mB0 + mi * 16) * FSTR + kb + aoff));
            ldsm4(bv2, smaddr(vts + dB0 * FSTR + kb + boff));
#pragma unroll
            for (int mi = 0; mi < 4; mi++)
#pragma unroll
                for (int nj = 0; nj < 2; nj++)
                    mma_tf32(kvacc[mi][nj], af[mi], &bv2[nj * 2]);
        }
    }

    float* outp = kvp + ((size_t)split * BB * HH + b * HH + h) * TWO_M * DH;
#pragma unroll
    for (int mi = 0; mi < 4; mi++)
#pragma unroll
        for (int nj = 0; nj < 2; nj++) {
            int m = mB0 + mi * 16 + g;
            int d = dB0 + nj * 8 + 2 * c;
            *(float2*)(outp + m * DH + d) =
                make_float2(kvacc[mi][nj][0], kvacc[mi][nj][1]);
            *(float2*)(outp + (m + 8) * DH + d) =
                make_float2(kvacc[mi][nj][2], kvacc[mi][nj][3]);
        }
}

// ---------------------------------------------------------------------------
__global__ void kv_reduce(const float4* __restrict__ kvp, float4* __restrict__ kv)
{
    const int N4 = BB * HH * TWO_M * DH / 4;
    int i = blockIdx.x * blockDim.x + threadIdx.x;
    if (i >= N4) return;
    float4 s = kvp[i];
#pragma unroll
    for (int sp = 1; sp < KV_SPLIT; sp++) {
        float4 t = kvp[(size_t)sp * N4 + i];
        s.x += t.x; s.y += t.y; s.z += t.z; s.w += t.w;
    }
    kv[i] = s;
}

// ---------------------------------------------------------------------------
// attn: out[tok,64] = q'[tok,256] @ kv[256,64] for batch bsel.
// ---------------------------------------------------------------------------
#define ACH 4
#define QSTR 260
#define ATTN_SMEM ((128*FSTR + 2*64*FSTR + 2*64*QSTR) * 4)

__global__ __launch_bounds__(512) void attn_mma(
    const float* __restrict__ Q, const float* __restrict__ kv,
    const float* __restrict__ proj, float* __restrict__ out, int bsel)
{
    extern __shared__ float sm[];
    float* projT = sm;
    float* qsh   = projT + 128 * FSTR;
    float* qsl   = qsh   + 64 * FSTR;
    float* qps   = qsl   + 64 * FSTR;
    float* kvt   = qps   + 64 * QSTR;

    const int h = blockIdx.y, b = bsel;
    const int tid = threadIdx.x;
    const int warp = tid >> 5, lane = tid & 31;
    const int g = lane >> 2, c = lane & 3;
    const int aoffF = AOFF(lane, FSTR);
    const int boffF = BOFF(lane, FSTR);
    const int aoffQ = AOFF(lane, QSTR);
    const int boffQ = BOFF(lane, QSTR);

    for (int it = tid; it < 2048; it += 512) {
        int d = it >> 5;
        int m4 = (it & 31) * 4;
        float4 pv = *(const float4*)(proj + d * MF + m4);
        projT[(m4 + 0) * FSTR + d] = tf32r(pv.x);
        projT[(m4 + 1) * FSTR + d] = tf32r(pv.y);
        projT[(m4 + 2) * FSTR + d] = tf32r(pv.z);
        projT[(m4 + 3) * FSTR + d] = tf32r(pv.w);
    }
    const float* kvsrc = kv + ((size_t)(b * HH + h)) * TWO_M * DH;
    for (int it = tid; it < 4096; it += 512) {
        int m = it >> 4;
        int d4 = (it & 15) * 4;
        float4 v = *(const float4*)(kvsrc + m * DH + d4);
        kvt[(d4 + 0) * QSTR + m] = tf32r(v.x);
        kvt[(d4 + 1) * QSTR + m] = tf32r(v.y);
        kvt[(d4 + 2) * QSTR + m] = tf32r(v.z);
        kvt[(d4 + 3) * QSTR + m] = tf32r(v.w);
    }

    const int wtokA = (warp & 3) * 16, wmA = (warp >> 2) * 32;
    const int tokB = (warp & 3) * 16, dB = (warp >> 2) * 16;

    for (int cc = 0; cc < ACH; cc++) {
        const int l0 = (blockIdx.x * ACH + cc) * 64;
        __syncthreads();
        for (int it = tid; it < 1024; it += 512) {
            int t = it >> 4;
            int d4 = (it & 15) * 4;
            size_t row = (size_t)(b * LL + l0 + t) * DM + h * DH + d4;
            float4 qv = *(const float4*)(Q + row);
            float hx = tf32r(qv.x), hy = tf32r(qv.y), hz = tf32r(qv.z), hw = tf32r(qv.w);
            *(float4*)&qsh[t * FSTR + d4] = make_float4(hx, hy, hz, hw);
            *(float4*)&qsl[t * FSTR + d4] = make_float4(
                tf32r(qv.x - hx), tf32r(qv.y - hy), tf32r(qv.z - hz), tf32r(qv.w - hw));
        }
        __syncthreads();

        float pacc[4][4];
#pragma unroll
        for (int nj = 0; nj < 4; nj++)
#pragma unroll
            for (int r = 0; r < 4; r++) pacc[nj][r] = 0.f;

#pragma unroll
        for (int ks = 0; ks < 8; ks++) {
            const int kb = ks * 8;
            uint32_t ah[4], al[4], bfr[2][4];
            ldsm4(ah, smaddr(qsh + wtokA * FSTR + kb + aoffF));
            ldsm4(al, smaddr(qsl + wtokA * FSTR + kb + aoffF));
            ldsm4(bfr[0], smaddr(projT + wmA * FSTR + kb + boffF));
            ldsm4(bfr[1], smaddr(projT + (wmA + 16) * FSTR + kb + boffF));
#pragma unroll
            for (int nj = 0; nj < 4; nj++) {
                mma_tf32(pacc[nj], ah, &bfr[nj >> 1][(nj & 1) * 2]);
                mma_tf32(pacc[nj], al, &bfr[nj >> 1][(nj & 1) * 2]);
            }
        }

#pragma unroll
        for (int nj = 0; nj < 4; nj++)
#pragma unroll
            for (int half = 0; half < 2; half++) {
                int tok = wtokA + g + half * 8;
                int m0 = wmA + nj * 8 + 2 * c;
                float p0 = pacc[nj][half * 2 + 0] * INV_SQRT_DH;
                float p1 = pacc[nj][half * 2 + 1] * INV_SQRT_DH;
                *(float2*)&qps[tok * QSTR + m0] = make_float2(
                    tf32r(__cosf(p0) * INV_SQRT_MF), tf32r(__cosf(p1) * INV_SQRT_MF));
                *(float2*)&qps[tok * QSTR + m0 + 128] = make_float2(
                    tf32r(__sinf(p0) * INV_SQRT_MF), tf32r(__sinf(p1) * INV_SQRT_MF));
            }
        __syncthreads();

        float oacc[2][4];
#pragma unroll
        for (int nj = 0; nj < 2; nj++)
#pragma unroll
            for (int r = 0; r < 4; r++) oacc[nj][r] = 0.f;

#pragma unroll
        for (int ks = 0; ks < 32; ks++) {
            const int kb = ks * 8;
            uint32_t af[4], bv2[4];
            ldsm4(af, smaddr(qps + tokB * QSTR + kb + aoffQ));
            ldsm4(bv2, smaddr(kvt + dB * QSTR + kb + boffQ));
#pragma unroll
            for (int nj = 0; nj < 2; nj++)
                mma_tf32(oacc[nj], af, &bv2[nj * 2]);
        }

#pragma unroll
        for (int nj = 0; nj < 2; nj++) {
            int tok = l0 + tokB + g;
            int col = h * DH + dB + nj * 8 + 2 * c;
            *(float2*)(out + (size_t)(b * LL + tok) * DM + col) =
                make_float2(tf32r(oacc[nj][0]), tf32r(oacc[nj][1]));
            *(float2*)(out + (size_t)(b * LL + tok + 8) * DM + col) =
                make_float2(tf32r(oacc[nj][2]), tf32r(oacc[nj][3]));
        }
    }
}

// ---------------------------------------------------------------------------
extern "C" void kernel_launch(void* const* d_in, const int* in_sizes, int n_in,
                              void* d_out, int out_size)
{
    const float* x    = (const float*)d_in[0];
    const float* proj = (const float*)d_in[1];
    const float* Wq   = (const float*)d_in[2];
    const float* bq   = (const float*)d_in[3];
    const float* Wk   = (const float*)d_in[4];
    const float* bk   = (const float*)d_in[5];
    const float* Wv   = (const float*)d_in[6];
    const float* bv   = (const float*)d_in[7];
    const float* Wo   = (const float*)d_in[8];
    const float* bo   = (const float*)d_in[9];
    float* out = (float*)d_out;

    float *q, *k, *v, *att, *wr, *kvp, *kvf;
    cudaGetSymbolAddress((void**)&q,   g_q);
    cudaGetSymbolAddress((void**)&k,   g_k);
    cudaGetSymbolAddress((void**)&v,   g_v);
    cudaGetSymbolAddress((void**)&att, g_att);
    cudaGetSymbolAddress((void**)&wr,  g_wr);
    cudaGetSymbolAddress((void**)&kvp, g_kvp);
    cudaGetSymbolAddress((void**)&kvf, g_kv);

    static cudaStream_t s2 = nullptr, s3 = nullptr;
    static cudaEvent_t evFork = nullptr, evJoin = nullptr;
    static cudaEvent_t evKV[BB], evA[BB];
    static bool init_done = false;
    if (!init_done) {
        cudaFuncSetAttribute(kv_gemm, cudaFuncAttributeMaxDynamicSharedMemorySize, GSMEM);
        cudaFuncSetAttribute(gemm_one, cudaFuncAttributeMaxDynamicSharedMemorySize, GSMEM);
        cudaFuncSetAttribute(feat_kv, cudaFuncAttributeMaxDynamicSharedMemorySize, FEAT_SMEM);
        cudaFuncSetAttribute(attn_mma, cudaFuncAttributeMaxDynamicSharedMemorySize, ATTN_SMEM);
        cudaStreamCreateWithFlags(&s2, cudaStreamNonBlocking);
        cudaStreamCreateWithFlags(&s3, cudaStreamNonBlocking);
        cudaEventCreateWithFlags(&evFork, cudaEventDisableTiming);
        cudaEventCreateWithFlags(&evJoin, cudaEventDisableTiming);
        for (int b = 0; b < BB; b++) {
            cudaEventCreateWithFlags(&evKV[b], cudaEventDisableTiming);
            cudaEventCreateWithFlags(&evA[b], cudaEventDisableTiming);
        }
        init_done = true;
    }

    const int WN4ALL = DM * DM;
    round_w<<<(WN4ALL + 255) / 256, 256>>>(
        (const float4*)Wq, (const float4*)Wk, (const float4*)Wv, (const float4*)Wo,
        (float4*)wr);

    // fork: Q-projection on s2, concurrent with the K/V + feature chain
    cudaEventRecord(evFork, 0);
    cudaStreamWaitEvent(s2, evFork, 0);
    gemm_one<<<dim3(DM / 128, TT / 128), 256, GSMEM, s2>>>(x, wr + 0 * DM * DM, bq, q);
    cudaEventRecord(evJoin, s2);

    // pipeline 1: kv_gemm(b) on stream 0  ->  feat_kv(b) on s3
    for (int b = 0; b < BB; b++) {
        size_t off = (size_t)b * LL * DM;
        kv_gemm<<<dim3(DM / 128, LL / 128, 2), 256, GSMEM>>>(
            x + off, wr, bk, bv, k + off, v + off);
        cudaEventRecord(evKV[b], 0);
        cudaStreamWaitEvent(s3, evKV[b], 0);
        feat_kv<<<dim3(KV_SPLIT, HH, 1), 512, FEAT_SMEM, s3>>>(k, v, proj, kvp, b);
    }

    const int N4 = BB * HH * TWO_M * DH / 4;
    kv_reduce<<<(N4 + 255) / 256, 256, 0, s3>>>((const float4*)kvp, (float4*)kvf);

    // pipeline 2: attn(b) on s3  ->  o_gemm(b) on stream 0
    cudaStreamWaitEvent(s3, evJoin, 0);
    for (int b = 0; b < BB; b++) {
        attn_mma<<<dim3(LL / (64 * ACH), HH, 1), 512, ATTN_SMEM, s3>>>(
            q, kvf, proj, att, b);
        cudaEventRecord(evA[b], s3);
        cudaStreamWaitEvent(0, evA[b], 0);
        size_t off = (size_t)b * LL * DM;
        gemm_one<<<dim3(DM / 128, LL / 128), 256, GSMEM>>>(
            att + off, wr + 3 * DM * DM, bo, out + off);
    }
}

// round 11
// speedup vs baseline: 1.0645x; 1.0645x over previous
#include <cuda_runtime.h>
#include <math.h>
#include <stdint.h>

#define BB 4
#define LL 4096
#define TT (BB*LL)
#define DM 1024
#define HH 16
#define DH 64
#define MF 128
#define TWO_M 256
#define KV_SPLIT 16
#define LSPLIT (LL/KV_SPLIT)   // 256

#define INV_SQRT_DH 0.125f
#define INV_SQRT_MF 0.08838834764831843f

__device__ float g_q[TT*DM];
__device__ float g_k[TT*DM];
__device__ float g_v[TT*DM];
__device__ float g_att[TT*DM];
__device__ float g_wr[4*DM*DM];
__device__ float g_kvp[(size_t)KV_SPLIT*BB*HH*TWO_M*DH];
__device__ float g_kv[(size_t)BB*HH*TWO_M*DH];

__device__ __forceinline__ float tf32r(float x) {
    uint32_t u;
    asm("cvt.rna.tf32.f32 %0, %1;" : "=r"(u) : "f"(x));
    return __uint_as_float(u);
}

__device__ __forceinline__ void mma_tf32(float* d, const uint32_t* a, const uint32_t* b) {
    asm volatile(
        "mma.sync.aligned.m16n8k8.row.col.f32.tf32.tf32.f32 "
        "{%0,%1,%2,%3}, {%4,%5,%6,%7}, {%8,%9}, {%0,%1,%2,%3};\n"
        : "+f"(d[0]), "+f"(d[1]), "+f"(d[2]), "+f"(d[3])
        : "r"(a[0]), "r"(a[1]), "r"(a[2]), "r"(a[3]), "r"(b[0]), "r"(b[1]));
}

__device__ __forceinline__ uint32_t smaddr(const void* p) {
    return (uint32_t)__cvta_generic_to_shared(p);
}

__device__ __forceinline__ void ldsm4(uint32_t* r, uint32_t a) {
    asm volatile("ldmatrix.sync.aligned.m8n8.x4.shared.b16 {%0,%1,%2,%3}, [%4];"
                 : "=r"(r[0]), "=r"(r[1]), "=r"(r[2]), "=r"(r[3]) : "r"(a));
}

#define AOFF(lane, STR) (((((lane) >> 3) & 1) * 8 + ((lane) & 7)) * (STR) + ((lane) >> 4) * 4)
#define BOFF(lane, STR) ((((lane) >> 4) * 8 + ((lane) & 7)) * (STR) + (((lane) >> 3) & 1) * 4)

// ---------------------------------------------------------------------------
__global__ void round_w(const float4* __restrict__ wq, const float4* __restrict__ wk,
                        const float4* __restrict__ wv, const float4* __restrict__ wo,
                        float4* __restrict__ dst)
{
    const int WN4 = DM * DM / 4;
    int i = blockIdx.x * 256 + threadIdx.x;
    if (i >= 4 * WN4) return;
    int sel = i / WN4, off = i - sel * WN4;
    const float4* src = (sel == 0) ? wq : (sel == 1) ? wk : (sel == 2) ? wv : wo;
    float4 v = src[off];
    v.x = tf32r(v.x); v.y = tf32r(v.y); v.z = tf32r(v.z); v.w = tf32r(v.w);
    dst[i] = v;
}

// ---------------------------------------------------------------------------
// GEMM body: C[128,128 tile] = A[M,1024] * W[N,1024]^T + bias
// ---------------------------------------------------------------------------
#define GS 3
#define GSTR 36
#define GSTAGE (128*GSTR)
#define GSMEM (2*GS*GSTAGE*4)

__device__ __forceinline__ void gemm_body(
    const float* __restrict__ A, const float* __restrict__ W,
    const float* __restrict__ bias, float* __restrict__ C)
{
    extern __shared__ float sg[];
    float* As = sg;
    float* Ws = sg + GS * GSTAGE;

    const int tid = threadIdx.x;
    const int bm = blockIdx.y * 128;
    const int bn = blockIdx.x * 128;
    const int warp = tid >> 5, lane = tid & 31;
    const int wm = (warp & 1) * 64;
    const int wn = (warp >> 1) * 32;
    const int g = lane >> 2, c = lane & 3;
    const int aoff = AOFF(lane, GSTR);
    const int boff = BOFF(lane, GSTR);

    float d[4][4][4];
#pragma unroll
    for (int mt = 0; mt < 4; mt++)
#pragma unroll
        for (int nt = 0; nt < 4; nt++)
#pragma unroll
            for (int r = 0; r < 4; r++) d[mt][nt][r] = 0.f;

    auto issue = [&](int st, int k0) {
#pragma unroll
        for (int j = 0; j < 4; j++) {
            int id = tid + j * 256;
            int row = id >> 3, kq = (id & 7) * 4;
            asm volatile("cp.async.cg.shared.global [%0], [%1], 16;\n"
                         :: "r"(smaddr(&As[st * GSTAGE + row * GSTR + kq])),
                            "l"(A + (size_t)(bm + row) * DM + k0 + kq));
            asm volatile("cp.async.cg.shared.global [%0], [%1], 16;\n"
                         :: "r"(smaddr(&Ws[st * GSTAGE + row * GSTR + kq])),
                            "l"(W + (size_t)(bn + row) * DM + k0 + kq));
        }
    };

    issue(0, 0);  asm volatile("cp.async.commit_group;\n");
    issue(1, 32); asm volatile("cp.async.commit_group;\n");

    const int NIT = DM / 32;
    for (int i = 0; i < NIT; i++) {
        asm volatile("cp.async.wait_group 1;\n");
        __syncthreads();
        if (i + 2 < NIT) issue((i + 2) % GS, (i + 2) * 32);
        asm volatile("cp.async.commit_group;\n");

        const float* Ab = As + (i % GS) * GSTAGE;
        const float* Wb = Ws + (i % GS) * GSTAGE;
#pragma unroll
        for (int ks = 0; ks < 4; ks++) {
            const int kb = ks * 8;
            uint32_t a[4][4], bq2[2][4];
#pragma unroll
            for (int mt = 0; mt < 4; mt++)
                ldsm4(a[mt], smaddr(Ab + (wm + mt * 16) * GSTR + kb + aoff));
            ldsm4(bq2[0], smaddr(Wb + wn * GSTR + kb + boff));
            ldsm4(bq2[1], smaddr(Wb + (wn + 16) * GSTR + kb + boff));
#pragma unroll
            for (int mt = 0; mt < 4; mt++)
#pragma unroll
                for (int nt = 0; nt < 4; nt++)
                    mma_tf32(d[mt][nt], a[mt], &bq2[nt >> 1][(nt & 1) * 2]);
        }
    }

#pragma unroll
    for (int nt = 0; nt < 4; nt++) {
        int col = bn + wn + nt * 8 + 2 * c;
        float b0 = bias[col], b1 = bias[col + 1];
#pragma unroll
        for (int mt = 0; mt < 4; mt++) {
            int row = bm + wm + mt * 16 + g;
            *(float2*)(C + (size_t)row * DM + col) =
                make_float2(d[mt][nt][0] + b0, d[mt][nt][1] + b1);
            *(float2*)(C + (size_t)(row + 8) * DM + col) =
                make_float2(d[mt][nt][2] + b0, d[mt][nt][3] + b1);
        }
    }
}

__global__ __launch_bounds__(256, 2) void kv_gemm(
    const float* __restrict__ A, const float* __restrict__ Wr,
    const float* __restrict__ bk, const float* __restrict__ bv,
    float* __restrict__ k, float* __restrict__ v)
{
    int z = blockIdx.z;   // 0 -> K, 1 -> V
    const float* W = Wr + (size_t)(z + 1) * DM * DM;
    const float* bias = (z == 0) ? bk : bv;
    float* C = (z == 0) ? k : v;
    gemm_body(A, W, bias, C);
}

__global__ __launch_bounds__(256, 2) void gemm_one(
    const float* __restrict__ A, const float* __restrict__ W,
    const float* __restrict__ bias, float* __restrict__ C)
{
    gemm_body(A, W, bias, C);
}

// ---------------------------------------------------------------------------
// feat_kv: per (split,h,b0+bz): kv[256,64] = sum_l k'(l)^T v(l). 512 threads.
// ---------------------------------------------------------------------------
#define FSTR 68
#define FEAT_SMEM ((128*FSTR + 3*64*FSTR + 256*FSTR) * 4)

__global__ __launch_bounds__(512) void feat_kv(
    const float* __restrict__ Kmat, const float* __restrict__ Vmat,
    const float* __restrict__ proj, float* __restrict__ kvp, int b0)
{
    extern __shared__ float sm[];
    float* projT = sm;
    float* ksh   = projT + 128 * FSTR;
    float* ksl   = ksh   + 64 * FSTR;
    float* vts   = ksl   + 64 * FSTR;
    float* kpt   = vts   + 64 * FSTR;

    const int split = blockIdx.x, h = blockIdx.y, b = b0 + blockIdx.z;
    const int tid = threadIdx.x;
    const int warp = tid >> 5, lane = tid & 31;
    const int g = lane >> 2, c = lane & 3;
    const int aoff = AOFF(lane, FSTR);
    const int boff = BOFF(lane, FSTR);

    for (int it = tid; it < 2048; it += 512) {
        int d = it >> 5;
        int m4 = (it & 31) * 4;
        float4 pv = *(const float4*)(proj + d * MF + m4);
        projT[(m4 + 0) * FSTR + d] = tf32r(pv.x);
        projT[(m4 + 1) * FSTR + d] = tf32r(pv.y);
        projT[(m4 + 2) * FSTR + d] = tf32r(pv.z);
        projT[(m4 + 3) * FSTR + d] = tf32r(pv.w);
    }

    float kvacc[4][2][4];
#pragma unroll
    for (int mi = 0; mi < 4; mi++)
#pragma unroll
        for (int nj = 0; nj < 2; nj++)
#pragma unroll
            for (int r = 0; r < 4; r++) kvacc[mi][nj][r] = 0.f;

    const int wtokA = (warp & 3) * 16, wmA = (warp >> 2) * 32;
    const int mB0 = (warp & 3) * 64, dB0 = (warp >> 2) * 16;
    const int l0 = split * LSPLIT;

    for (int ch = 0; ch < LSPLIT; ch += 64) {
        __syncthreads();
        for (int it = tid; it < 1024; it += 512) {
            int t = it >> 4;
            int d4 = (it & 15) * 4;
            size_t row = (size_t)(b * LL + l0 + ch + t) * DM + h * DH + d4;
            float4 kvv = *(const float4*)(Kmat + row);
            float hx = tf32r(kvv.x), hy = tf32r(kvv.y), hz = tf32r(kvv.z), hw = tf32r(kvv.w);
            *(float4*)&ksh[t * FSTR + d4] = make_float4(hx, hy, hz, hw);
            *(float4*)&ksl[t * FSTR + d4] = make_float4(
                tf32r(kvv.x - hx), tf32r(kvv.y - hy), tf32r(kvv.z - hz), tf32r(kvv.w - hw));
            float4 vv = *(const float4*)(Vmat + row);
            vts[(d4 + 0) * FSTR + t] = tf32r(vv.x);
            vts[(d4 + 1) * FSTR + t] = tf32r(vv.y);
            vts[(d4 + 2) * FSTR + t] = tf32r(vv.z);
            vts[(d4 + 3) * FSTR + t] = tf32r(vv.w);
        }
        __syncthreads();

        float pacc[4][4];
#pragma unroll
        for (int nj = 0; nj < 4; nj++)
#pragma unroll
            for (int r = 0; r < 4; r++) pacc[nj][r] = 0.f;

#pragma unroll
        for (int ks = 0; ks < 8; ks++) {
            const int kb = ks * 8;
            uint32_t ah[4], al[4], bfr[2][4];
            ldsm4(ah, smaddr(ksh + wtokA * FSTR + kb + aoff));
            ldsm4(al, smaddr(ksl + wtokA * FSTR + kb + aoff));
            ldsm4(bfr[0], smaddr(projT + wmA * FSTR + kb + boff));
            ldsm4(bfr[1], smaddr(projT + (wmA + 16) * FSTR + kb + boff));
#pragma unroll
            for (int nj = 0; nj < 4; nj++) {
                mma_tf32(pacc[nj], ah, &bfr[nj >> 1][(nj & 1) * 2]);
                mma_tf32(pacc[nj], al, &bfr[nj >> 1][(nj & 1) * 2]);
            }
        }

#pragma unroll
        for (int nj = 0; nj < 4; nj++)
#pragma unroll
            for (int r = 0; r < 4; r++) {
                int tok = wtokA + g + (r >> 1) * 8;
                int m = wmA + nj * 8 + 2 * c + (r & 1);
                float p = pacc[nj][r] * INV_SQRT_DH;
                kpt[m * FSTR + tok] = tf32r(__cosf(p) * INV_SQRT_MF);
                kpt[(m + 128) * FSTR + tok] = tf32r(__sinf(p) * INV_SQRT_MF);
            }
        __syncthreads();

#pragma unroll
        for (int ks = 0; ks < 8; ks++) {
            const int kb = ks * 8;
            uint32_t af[4][4], bv2[4];
#pragma unroll
            for (int mi = 0; mi < 4; mi++)
                ldsm4(af[mi], smaddr(kpt + (mB0 + mi * 16) * FSTR + kb + aoff));
            ldsm4(bv2, smaddr(vts + dB0 * FSTR + kb + boff));
#pragma unroll
            for (int mi = 0; mi < 4; mi++)
#pragma unroll
                for (int nj = 0; nj < 2; nj++)
                    mma_tf32(kvacc[mi][nj], af[mi], &bv2[nj * 2]);
        }
    }

    float* outp = kvp + ((size_t)split * BB * HH + b * HH + h) * TWO_M * DH;
#pragma unroll
    for (int mi = 0; mi < 4; mi++)
#pragma unroll
        for (int nj = 0; nj < 2; nj++) {
            int m = mB0 + mi * 16 + g;
            int d = dB0 + nj * 8 + 2 * c;
            *(float2*)(outp + m * DH + d) =
                make_float2(kvacc[mi][nj][0], kvacc[mi][nj][1]);
            *(float2*)(outp + (m + 8) * DH + d) =
                make_float2(kvacc[mi][nj][2], kvacc[mi][nj][3]);
        }
}

// ---------------------------------------------------------------------------
__global__ void kv_reduce(const float4* __restrict__ kvp, float4* __restrict__ kv)
{
    const int N4 = BB * HH * TWO_M * DH / 4;
    int i = blockIdx.x * blockDim.x + threadIdx.x;
    if (i >= N4) return;
    float4 s = kvp[i];
#pragma unroll
    for (int sp = 1; sp < KV_SPLIT; sp++) {
        float4 t = kvp[(size_t)sp * N4 + i];
        s.x += t.x; s.y += t.y; s.z += t.z; s.w += t.w;
    }
    kv[i] = s;
}

// ---------------------------------------------------------------------------
// attn: out[tok,64] = q'[tok,256] @ kv[256,64] for batch b0+bz.
// ---------------------------------------------------------------------------
#define ACH 4
#define QSTR 260
#define ATTN_SMEM ((128*FSTR + 2*64*FSTR + 2*64*QSTR) * 4)

__global__ __launch_bounds__(512) void attn_mma(
    const float* __restrict__ Q, const float* __restrict__ kv,
    const float* __restrict__ proj, float* __restrict__ out, int b0)
{
    extern __shared__ float sm[];
    float* projT = sm;
    float* qsh   = projT + 128 * FSTR;
    float* qsl   = qsh   + 64 * FSTR;
    float* qps   = qsl   + 64 * FSTR;
    float* kvt   = qps   + 64 * QSTR;

    const int h = blockIdx.y, b = b0 + blockIdx.z;
    const int tid = threadIdx.x;
    const int warp = tid >> 5, lane = tid & 31;
    const int g = lane >> 2, c = lane & 3;
    const int aoffF = AOFF(lane, FSTR);
    const int boffF = BOFF(lane, FSTR);
    const int aoffQ = AOFF(lane, QSTR);
    const int boffQ = BOFF(lane, QSTR);

    for (int it = tid; it < 2048; it += 512) {
        int d = it >> 5;
        int m4 = (it & 31) * 4;
        float4 pv = *(const float4*)(proj + d * MF + m4);
        projT[(m4 + 0) * FSTR + d] = tf32r(pv.x);
        projT[(m4 + 1) * FSTR + d] = tf32r(pv.y);
        projT[(m4 + 2) * FSTR + d] = tf32r(pv.z);
        projT[(m4 + 3) * FSTR + d] = tf32r(pv.w);
    }
    const float* kvsrc = kv + ((size_t)(b * HH + h)) * TWO_M * DH;
    for (int it = tid; it < 4096; it += 512) {
        int m = it >> 4;
        int d4 = (it & 15) * 4;
        float4 v = *(const float4*)(kvsrc + m * DH + d4);
        kvt[(d4 + 0) * QSTR + m] = tf32r(v.x);
        kvt[(d4 + 1) * QSTR + m] = tf32r(v.y);
        kvt[(d4 + 2) * QSTR + m] = tf32r(v.z);
        kvt[(d4 + 3) * QSTR + m] = tf32r(v.w);
    }

    const int wtokA = (warp & 3) * 16, wmA = (warp >> 2) * 32;
    const int tokB = (warp & 3) * 16, dB = (warp >> 2) * 16;

    for (int cc = 0; cc < ACH; cc++) {
        const int l0 = (blockIdx.x * ACH + cc) * 64;
        __syncthreads();
        for (int it = tid; it < 1024; it += 512) {
            int t = it >> 4;
            int d4 = (it & 15) * 4;
            size_t row = (size_t)(b * LL + l0 + t) * DM + h * DH + d4;
            float4 qv = *(const float4*)(Q + row);
            float hx = tf32r(qv.x), hy = tf32r(qv.y), hz = tf32r(qv.z), hw = tf32r(qv.w);
            *(float4*)&qsh[t * FSTR + d4] = make_float4(hx, hy, hz, hw);
            *(float4*)&qsl[t * FSTR + d4] = make_float4(
                tf32r(qv.x - hx), tf32r(qv.y - hy), tf32r(qv.z - hz), tf32r(qv.w - hw));
        }
        __syncthreads();

        float pacc[4][4];
#pragma unroll
        for (int nj = 0; nj < 4; nj++)
#pragma unroll
            for (int r = 0; r < 4; r++) pacc[nj][r] = 0.f;

#pragma unroll
        for (int ks = 0; ks < 8; ks++) {
            const int kb = ks * 8;
            uint32_t ah[4], al[4], bfr[2][4];
            ldsm4(ah, smaddr(qsh + wtokA * FSTR + kb + aoffF));
            ldsm4(al, smaddr(qsl + wtokA * FSTR + kb + aoffF));
            ldsm4(bfr[0], smaddr(projT + wmA * FSTR + kb + boffF));
            ldsm4(bfr[1], smaddr(projT + (wmA + 16) * FSTR + kb + boffF));
#pragma unroll
            for (int nj = 0; nj < 4; nj++) {
                mma_tf32(pacc[nj], ah, &bfr[nj >> 1][(nj & 1) * 2]);
                mma_tf32(pacc[nj], al, &bfr[nj >> 1][(nj & 1) * 2]);
            }
        }

#pragma unroll
        for (int nj = 0; nj < 4; nj++)
#pragma unroll
            for (int half = 0; half < 2; half++) {
                int tok = wtokA + g + half * 8;
                int m0 = wmA + nj * 8 + 2 * c;
                float p0 = pacc[nj][half * 2 + 0] * INV_SQRT_DH;
                float p1 = pacc[nj][half * 2 + 1] * INV_SQRT_DH;
                *(float2*)&qps[tok * QSTR + m0] = make_float2(
                    tf32r(__cosf(p0) * INV_SQRT_MF), tf32r(__cosf(p1) * INV_SQRT_MF));
                *(float2*)&qps[tok * QSTR + m0 + 128] = make_float2(
                    tf32r(__sinf(p0) * INV_SQRT_MF), tf32r(__sinf(p1) * INV_SQRT_MF));
            }
        __syncthreads();

        float oacc[2][4];
#pragma unroll
        for (int nj = 0; nj < 2; nj++)
#pragma unroll
            for (int r = 0; r < 4; r++) oacc[nj][r] = 0.f;

#pragma unroll
        for (int ks = 0; ks < 32; ks++) {
            const int kb = ks * 8;
            uint32_t af[4], bv2[4];
            ldsm4(af, smaddr(qps + tokB * QSTR + kb + aoffQ));
            ldsm4(bv2, smaddr(kvt + dB * QSTR + kb + boffQ));
#pragma unroll
            for (int nj = 0; nj < 2; nj++)
                mma_tf32(oacc[nj], af, &bv2[nj * 2]);
        }

#pragma unroll
        for (int nj = 0; nj < 2; nj++) {
            int tok = l0 + tokB + g;
            int col = h * DH + dB + nj * 8 + 2 * c;
            *(float2*)(out + (size_t)(b * LL + tok) * DM + col) =
                make_float2(tf32r(oacc[nj][0]), tf32r(oacc[nj][1]));
            *(float2*)(out + (size_t)(b * LL + tok + 8) * DM + col) =
                make_float2(tf32r(oacc[nj][2]), tf32r(oacc[nj][3]));
        }
    }
}

// ---------------------------------------------------------------------------
extern "C" void kernel_launch(void* const* d_in, const int* in_sizes, int n_in,
                              void* d_out, int out_size)
{
    const float* x    = (const float*)d_in[0];
    const float* proj = (const float*)d_in[1];
    const float* Wq   = (const float*)d_in[2];
    const float* bq   = (const float*)d_in[3];
    const float* Wk   = (const float*)d_in[4];
    const float* bk   = (const float*)d_in[5];
    const float* Wv   = (const float*)d_in[6];
    const float* bv   = (const float*)d_in[7];
    const float* Wo   = (const float*)d_in[8];
    const float* bo   = (const float*)d_in[9];
    float* out = (float*)d_out;

    float *q, *k, *v, *att, *wr, *kvp, *kvf;
    cudaGetSymbolAddress((void**)&q,   g_q);
    cudaGetSymbolAddress((void**)&k,   g_k);
    cudaGetSymbolAddress((void**)&v,   g_v);
    cudaGetSymbolAddress((void**)&att, g_att);
    cudaGetSymbolAddress((void**)&wr,  g_wr);
    cudaGetSymbolAddress((void**)&kvp, g_kvp);
    cudaGetSymbolAddress((void**)&kvf, g_kv);

    static cudaStream_t s2 = nullptr, s3 = nullptr;
    static cudaEvent_t evFork = nullptr, evJoin = nullptr;
    static cudaEvent_t evKV[2], evA[2];
    static bool init_done = false;
    if (!init_done) {
        cudaFuncSetAttribute(kv_gemm, cudaFuncAttributeMaxDynamicSharedMemorySize, GSMEM);
        cudaFuncSetAttribute(gemm_one, cudaFuncAttributeMaxDynamicSharedMemorySize, GSMEM);
        cudaFuncSetAttribute(feat_kv, cudaFuncAttributeMaxDynamicSharedMemorySize, FEAT_SMEM);
        cudaFuncSetAttribute(attn_mma, cudaFuncAttributeMaxDynamicSharedMemorySize, ATTN_SMEM);
        cudaStreamCreateWithFlags(&s2, cudaStreamNonBlocking);
        cudaStreamCreateWithFlags(&s3, cudaStreamNonBlocking);
        cudaEventCreateWithFlags(&evFork, cudaEventDisableTiming);
        cudaEventCreateWithFlags(&evJoin, cudaEventDisableTiming);
        for (int h = 0; h < 2; h++) {
            cudaEventCreateWithFlags(&evKV[h], cudaEventDisableTiming);
            cudaEventCreateWithFlags(&evA[h], cudaEventDisableTiming);
        }
        init_done = true;
    }

    const int WN4ALL = DM * DM;
    round_w<<<(WN4ALL + 255) / 256, 256>>>(
        (const float4*)Wq, (const float4*)Wk, (const float4*)Wv, (const float4*)Wo,
        (float4*)wr);

    // fork: Q-projection on s2 (overlaps the K/V + feature chain)
    cudaEventRecord(evFork, 0);
    cudaStreamWaitEvent(s2, evFork, 0);
    gemm_one<<<dim3(DM / 128, TT / 128), 256, GSMEM, s2>>>(x, wr + 0 * DM * DM, bq, q);
    cudaEventRecord(evJoin, s2);

    // pipeline 1 (half granularity): kv_gemm(half) stream0 -> feat_kv(half) s3
    const int HB = BB / 2;   // 2 batches per half
    for (int hf = 0; hf < 2; hf++) {
        size_t off = (size_t)hf * HB * LL * DM;
        kv_gemm<<<dim3(DM / 128, HB * LL / 128, 2), 256, GSMEM>>>(
            x + off, wr, bk, bv, k + off, v + off);
        cudaEventRecord(evKV[hf], 0);
        cudaStreamWaitEvent(s3, evKV[hf], 0);
        feat_kv<<<dim3(KV_SPLIT, HH, HB), 512, FEAT_SMEM, s3>>>(
            k, v, proj, kvp, hf * HB);
    }

    const int N4 = BB * HH * TWO_M * DH / 4;
    kv_reduce<<<(N4 + 255) / 256, 256, 0, s3>>>((const float4*)kvp, (float4*)kvf);

    // pipeline 2 (half granularity): attn(half) s3 -> o_gemm(half) stream0
    cudaStreamWaitEvent(s3, evJoin, 0);
    for (int hf = 0; hf < 2; hf++) {
        attn_mma<<<dim3(LL / (64 * ACH), HH, HB), 512, ATTN_SMEM, s3>>>(
            q, kvf, proj, att, hf * HB);
        cudaEventRecord(evA[hf], s3);
        cudaStreamWaitEvent(0, evA[hf], 0);
        size_t off = (size_t)hf * HB * LL * DM;
        gemm_one<<<dim3(DM / 128, HB * LL / 128), 256, GSMEM>>>(
            att + off, wr + 3 * DM * DM, bo, out + off);
    }
}

// round 12
// speedup vs baseline: 1.1542x; 1.0843x over previous
#include <cuda_runtime.h>
#include <math.h>
#include <stdint.h>

#define BB 4
#define LL 4096
#define TT (BB*LL)
#define DM 1024
#define HH 16
#define DH 64
#define MF 128
#define TWO_M 256
#define KV_SPLIT 16
#define LSPLIT (LL/KV_SPLIT)   // 256

#define INV_SQRT_DH 0.125f
#define INV_SQRT_MF 0.08838834764831843f

__device__ float g_q[TT*DM];
__device__ float g_k[TT*DM];
__device__ float g_v[TT*DM];
__device__ float g_att[TT*DM];
__device__ float g_wr[4*DM*DM];
__device__ float g_kvp[(size_t)KV_SPLIT*BB*HH*TWO_M*DH];
__device__ float g_kv[(size_t)BB*HH*TWO_M*DH];

__device__ __forceinline__ float tf32r(float x) {
    uint32_t u;
    asm("cvt.rna.tf32.f32 %0, %1;" : "=r"(u) : "f"(x));
    return __uint_as_float(u);
}

__device__ __forceinline__ void mma_tf32(float* d, const uint32_t* a, const uint32_t* b) {
    asm volatile(
        "mma.sync.aligned.m16n8k8.row.col.f32.tf32.tf32.f32 "
        "{%0,%1,%2,%3}, {%4,%5,%6,%7}, {%8,%9}, {%0,%1,%2,%3};\n"
        : "+f"(d[0]), "+f"(d[1]), "+f"(d[2]), "+f"(d[3])
        : "r"(a[0]), "r"(a[1]), "r"(a[2]), "r"(a[3]), "r"(b[0]), "r"(b[1]));
}

__device__ __forceinline__ uint32_t smaddr(const void* p) {
    return (uint32_t)__cvta_generic_to_shared(p);
}

__device__ __forceinline__ void ldsm4(uint32_t* r, uint32_t a) {
    asm volatile("ldmatrix.sync.aligned.m8n8.x4.shared.b16 {%0,%1,%2,%3}, [%4];"
                 : "=r"(r[0]), "=r"(r[1]), "=r"(r[2]), "=r"(r[3]) : "r"(a));
}

#define AOFF(lane, STR) (((((lane) >> 3) & 1) * 8 + ((lane) & 7)) * (STR) + ((lane) >> 4) * 4)
#define BOFF(lane, STR) ((((lane) >> 4) * 8 + ((lane) & 7)) * (STR) + (((lane) >> 3) & 1) * 4)

// ---------------------------------------------------------------------------
__global__ void round_w(const float4* __restrict__ wq, const float4* __restrict__ wk,
                        const float4* __restrict__ wv, const float4* __restrict__ wo,
                        float4* __restrict__ dst)
{
    const int WN4 = DM * DM / 4;
    int i = blockIdx.x * 256 + threadIdx.x;
    if (i >= 4 * WN4) return;
    int sel = i / WN4, off = i - sel * WN4;
    const float4* src = (sel == 0) ? wq : (sel == 1) ? wk : (sel == 2) ? wv : wo;
    float4 v = src[off];
    v.x = tf32r(v.x); v.y = tf32r(v.y); v.z = tf32r(v.z); v.w = tf32r(v.w);
    dst[i] = v;
}

// ---------------------------------------------------------------------------
// GEMM body: C[128,128 tile] = A[M,1024] * W[N,1024]^T + bias
// cp.async 3-stage pipeline, ldmatrix fragment loads. 256 threads, 2 CTA/SM.
// ---------------------------------------------------------------------------
#define GS 3
#define GSTR 36
#define GSTAGE (128*GSTR)
#define GSMEM (2*GS*GSTAGE*4)

__device__ __forceinline__ void gemm_body(
    const float* __restrict__ A, const float* __restrict__ W,
    const float* __restrict__ bias, float* __restrict__ C)
{
    extern __shared__ float sg[];
    float* As = sg;
    float* Ws = sg + GS * GSTAGE;

    const int tid = threadIdx.x;
    const int bm = blockIdx.y * 128;
    const int bn = blockIdx.x * 128;
    const int warp = tid >> 5, lane = tid & 31;
    const int wm = (warp & 1) * 64;
    const int wn = (warp >> 1) * 32;
    const int g = lane >> 2, c = lane & 3;
    const int aoff = AOFF(lane, GSTR);
    const int boff = BOFF(lane, GSTR);

    float d[4][4][4];
#pragma unroll
    for (int mt = 0; mt < 4; mt++)
#pragma unroll
        for (int nt = 0; nt < 4; nt++)
#pragma unroll
            for (int r = 0; r < 4; r++) d[mt][nt][r] = 0.f;

    auto issue = [&](int st, int k0) {
#pragma unroll
        for (int j = 0; j < 4; j++) {
            int id = tid + j * 256;
            int row = id >> 3, kq = (id & 7) * 4;
            asm volatile("cp.async.cg.shared.global [%0], [%1], 16;\n"
                         :: "r"(smaddr(&As[st * GSTAGE + row * GSTR + kq])),
                            "l"(A + (size_t)(bm + row) * DM + k0 + kq));
            asm volatile("cp.async.cg.shared.global [%0], [%1], 16;\n"
                         :: "r"(smaddr(&Ws[st * GSTAGE + row * GSTR + kq])),
                            "l"(W + (size_t)(bn + row) * DM + k0 + kq));
        }
    };

    issue(0, 0);  asm volatile("cp.async.commit_group;\n");
    issue(1, 32); asm volatile("cp.async.commit_group;\n");

    const int NIT = DM / 32;
    for (int i = 0; i < NIT; i++) {
        asm volatile("cp.async.wait_group 1;\n");
        __syncthreads();
        if (i + 2 < NIT) issue((i + 2) % GS, (i + 2) * 32);
        asm volatile("cp.async.commit_group;\n");

        const float* Ab = As + (i % GS) * GSTAGE;
        const float* Wb = Ws + (i % GS) * GSTAGE;
#pragma unroll
        for (int ks = 0; ks < 4; ks++) {
            const int kb = ks * 8;
            uint32_t a[4][4], bq2[2][4];
#pragma unroll
            for (int mt = 0; mt < 4; mt++)
                ldsm4(a[mt], smaddr(Ab + (wm + mt * 16) * GSTR + kb + aoff));
            ldsm4(bq2[0], smaddr(Wb + wn * GSTR + kb + boff));
            ldsm4(bq2[1], smaddr(Wb + (wn + 16) * GSTR + kb + boff));
#pragma unroll
            for (int mt = 0; mt < 4; mt++)
#pragma unroll
                for (int nt = 0; nt < 4; nt++)
                    mma_tf32(d[mt][nt], a[mt], &bq2[nt >> 1][(nt & 1) * 2]);
        }
    }

#pragma unroll
    for (int nt = 0; nt < 4; nt++) {
        int col = bn + wn + nt * 8 + 2 * c;
        float b0 = bias[col], b1 = bias[col + 1];
#pragma unroll
        for (int mt = 0; mt < 4; mt++) {
            int row = bm + wm + mt * 16 + g;
            *(float2*)(C + (size_t)row * DM + col) =
                make_float2(d[mt][nt][0] + b0, d[mt][nt][1] + b1);
            *(float2*)(C + (size_t)(row + 8) * DM + col) =
                make_float2(d[mt][nt][2] + b0, d[mt][nt][3] + b1);
        }
    }
}

__global__ __launch_bounds__(256, 2) void kv_gemm(
    const float* __restrict__ A, const float* __restrict__ Wr,
    const float* __restrict__ bk, const float* __restrict__ bv,
    float* __restrict__ k, float* __restrict__ v)
{
    int z = blockIdx.z;   // 0 -> K, 1 -> V
    const float* W = Wr + (size_t)(z + 1) * DM * DM;
    const float* bias = (z == 0) ? bk : bv;
    float* C = (z == 0) ? k : v;
    gemm_body(A, W, bias, C);
}

__global__ __launch_bounds__(256, 2) void gemm_one(
    const float* __restrict__ A, const float* __restrict__ W,
    const float* __restrict__ bias, float* __restrict__ C)
{
    gemm_body(A, W, bias, C);
}

// ---------------------------------------------------------------------------
// feat_kv: per (split,h,b): kv[256,64] = sum_l k'(l)^T v(l). 512 threads.
// Single tf32 phase MMA (no hi/lo split).
// ---------------------------------------------------------------------------
#define FSTR 68
#define FEAT_SMEM ((128*FSTR + 2*64*FSTR + 256*FSTR) * 4)   // 139264 B

__global__ __launch_bounds__(512) void feat_kv(
    const float* __restrict__ Kmat, const float* __restrict__ Vmat,
    const float* __restrict__ proj, float* __restrict__ kvp)
{
    extern __shared__ float sm[];
    float* projT = sm;                    // [128][68]
    float* ksh   = projT + 128 * FSTR;    // [64][68]
    float* vts   = ksh   + 64 * FSTR;     // [64 d][68 tok]
    float* kpt   = vts   + 64 * FSTR;     // [256 m'][68 tok]

    const int split = blockIdx.x, h = blockIdx.y, b = blockIdx.z;
    const int tid = threadIdx.x;
    const int warp = tid >> 5, lane = tid & 31;
    const int g = lane >> 2, c = lane & 3;
    const int aoff = AOFF(lane, FSTR);
    const int boff = BOFF(lane, FSTR);

    for (int it = tid; it < 2048; it += 512) {
        int d = it >> 5;
        int m4 = (it & 31) * 4;
        float4 pv = *(const float4*)(proj + d * MF + m4);
        projT[(m4 + 0) * FSTR + d] = tf32r(pv.x);
        projT[(m4 + 1) * FSTR + d] = tf32r(pv.y);
        projT[(m4 + 2) * FSTR + d] = tf32r(pv.z);
        projT[(m4 + 3) * FSTR + d] = tf32r(pv.w);
    }

    float kvacc[4][2][4];
#pragma unroll
    for (int mi = 0; mi < 4; mi++)
#pragma unroll
        for (int nj = 0; nj < 2; nj++)
#pragma unroll
            for (int r = 0; r < 4; r++) kvacc[mi][nj][r] = 0.f;

    const int wtokA = (warp & 3) * 16, wmA = (warp >> 2) * 32;
    const int mB0 = (warp & 3) * 64, dB0 = (warp >> 2) * 16;
    const int l0 = split * LSPLIT;

    for (int ch = 0; ch < LSPLIT; ch += 64) {
        __syncthreads();
        for (int it = tid; it < 1024; it += 512) {
            int t = it >> 4;
            int d4 = (it & 15) * 4;
            size_t row = (size_t)(b * LL + l0 + ch + t) * DM + h * DH + d4;
            float4 kvv = *(const float4*)(Kmat + row);
            *(float4*)&ksh[t * FSTR + d4] = make_float4(
                tf32r(kvv.x), tf32r(kvv.y), tf32r(kvv.z), tf32r(kvv.w));
            float4 vv = *(const float4*)(Vmat + row);
            vts[(d4 + 0) * FSTR + t] = tf32r(vv.x);
            vts[(d4 + 1) * FSTR + t] = tf32r(vv.y);
            vts[(d4 + 2) * FSTR + t] = tf32r(vv.z);
            vts[(d4 + 3) * FSTR + t] = tf32r(vv.w);
        }
        __syncthreads();

        // Step A: P[64,128] = K @ projT (single tf32 MMA)
        float pacc[4][4];
#pragma unroll
        for (int nj = 0; nj < 4; nj++)
#pragma unroll
            for (int r = 0; r < 4; r++) pacc[nj][r] = 0.f;

#pragma unroll
        for (int ks = 0; ks < 8; ks++) {
            const int kb = ks * 8;
            uint32_t ah[4], bfr[2][4];
            ldsm4(ah, smaddr(ksh + wtokA * FSTR + kb + aoff));
            ldsm4(bfr[0], smaddr(projT + wmA * FSTR + kb + boff));
            ldsm4(bfr[1], smaddr(projT + (wmA + 16) * FSTR + kb + boff));
#pragma unroll
            for (int nj = 0; nj < 4; nj++)
                mma_tf32(pacc[nj], ah, &bfr[nj >> 1][(nj & 1) * 2]);
        }

#pragma unroll
        for (int nj = 0; nj < 4; nj++)
#pragma unroll
            for (int r = 0; r < 4; r++) {
                int tok = wtokA + g + (r >> 1) * 8;
                int m = wmA + nj * 8 + 2 * c + (r & 1);
                float p = pacc[nj][r] * INV_SQRT_DH;
                kpt[m * FSTR + tok] = tf32r(__cosf(p) * INV_SQRT_MF);
                kpt[(m + 128) * FSTR + tok] = tf32r(__sinf(p) * INV_SQRT_MF);
            }
        __syncthreads();

        // Step B: kv[256,64] += k'T @ V
#pragma unroll
        for (int ks = 0; ks < 8; ks++) {
            const int kb = ks * 8;
            uint32_t af[4][4], bv2[4];
#pragma unroll
            for (int mi = 0; mi < 4; mi++)
                ldsm4(af[mi], smaddr(kpt + (mB0 + mi * 16) * FSTR + kb + aoff));
            ldsm4(bv2, smaddr(vts + dB0 * FSTR + kb + boff));
#pragma unroll
            for (int mi = 0; mi < 4; mi++)
#pragma unroll
                for (int nj = 0; nj < 2; nj++)
                    mma_tf32(kvacc[mi][nj], af[mi], &bv2[nj * 2]);
        }
    }

    float* outp = kvp + ((size_t)split * BB * HH + b * HH + h) * TWO_M * DH;
#pragma unroll
    for (int mi = 0; mi < 4; mi++)
#pragma unroll
        for (int nj = 0; nj < 2; nj++) {
            int m = mB0 + mi * 16 + g;
            int d = dB0 + nj * 8 + 2 * c;
            *(float2*)(outp + m * DH + d) =
                make_float2(kvacc[mi][nj][0], kvacc[mi][nj][1]);
            *(float2*)(outp + (m + 8) * DH + d) =
                make_float2(kvacc[mi][nj][2], kvacc[mi][nj][3]);
        }
}

// ---------------------------------------------------------------------------
__global__ void kv_reduce(const float4* __restrict__ kvp, float4* __restrict__ kv)
{
    const int N4 = BB * HH * TWO_M * DH / 4;
    int i = blockIdx.x * blockDim.x + threadIdx.x;
    if (i >= N4) return;
    float4 s = kvp[i];
#pragma unroll
    for (int sp = 1; sp < KV_SPLIT; sp++) {
        float4 t = kvp[(size_t)sp * N4 + i];
        s.x += t.x; s.y += t.y; s.z += t.z; s.w += t.w;
    }
    kv[i] = s;
}

// ---------------------------------------------------------------------------
// attn: out[tok,64] = q'[tok,256] @ kv[256,64]. 512 threads, ACH=8 chunks.
// Single tf32 phase MMA (no hi/lo split).
// ---------------------------------------------------------------------------
#define ACH 8
#define QSTR 260
#define ATTN_SMEM ((128*FSTR + 64*FSTR + 2*64*QSTR) * 4)   // 185344 B

__global__ __launch_bounds__(512) void attn_mma(
    const float* __restrict__ Q, const float* __restrict__ kv,
    const float* __restrict__ proj, float* __restrict__ out)
{
    extern __shared__ float sm[];
    float* projT = sm;                    // [128][68]
    float* qsh   = projT + 128 * FSTR;    // [64][68]
    float* qps   = qsh   + 64 * FSTR;     // [64 tok][260]
    float* kvt   = qps   + 64 * QSTR;     // [64 d][260 m']

    const int h = blockIdx.y, b = blockIdx.z;
    const int tid = threadIdx.x;
    const int warp = tid >> 5, lane = tid & 31;
    const int g = lane >> 2, c = lane & 3;
    const int aoffF = AOFF(lane, FSTR);
    const int boffF = BOFF(lane, FSTR);
    const int aoffQ = AOFF(lane, QSTR);
    const int boffQ = BOFF(lane, QSTR);

    for (int it = tid; it < 2048; it += 512) {
        int d = it >> 5;
        int m4 = (it & 31) * 4;
        float4 pv = *(const float4*)(proj + d * MF + m4);
        projT[(m4 + 0) * FSTR + d] = tf32r(pv.x);
        projT[(m4 + 1) * FSTR + d] = tf32r(pv.y);
        projT[(m4 + 2) * FSTR + d] = tf32r(pv.z);
        projT[(m4 + 3) * FSTR + d] = tf32r(pv.w);
    }
    const float* kvsrc = kv + ((size_t)(b * HH + h)) * TWO_M * DH;
    for (int it = tid; it < 4096; it += 512) {
        int m = it >> 4;
        int d4 = (it & 15) * 4;
        float4 v = *(const float4*)(kvsrc + m * DH + d4);
        kvt[(d4 + 0) * QSTR + m] = tf32r(v.x);
        kvt[(d4 + 1) * QSTR + m] = tf32r(v.y);
        kvt[(d4 + 2) * QSTR + m] = tf32r(v.z);
        kvt[(d4 + 3) * QSTR + m] = tf32r(v.w);
    }

    const int wtokA = (warp & 3) * 16, wmA = (warp >> 2) * 32;
    const int tokB = (warp & 3) * 16, dB = (warp >> 2) * 16;

    for (int cc = 0; cc < ACH; cc++) {
        const int l0 = (blockIdx.x * ACH + cc) * 64;
        __syncthreads();
        for (int it = tid; it < 1024; it += 512) {
            int t = it >> 4;
            int d4 = (it & 15) * 4;
            size_t row = (size_t)(b * LL + l0 + t) * DM + h * DH + d4;
            float4 qv = *(const float4*)(Q + row);
            *(float4*)&qsh[t * FSTR + d4] = make_float4(
                tf32r(qv.x), tf32r(qv.y), tf32r(qv.z), tf32r(qv.w));
        }
        __syncthreads();

        // Step A: P = Q @ projT (single tf32 MMA)
        float pacc[4][4];
#pragma unroll
        for (int nj = 0; nj < 4; nj++)
#pragma unroll
            for (int r = 0; r < 4; r++) pacc[nj][r] = 0.f;

#pragma unroll
        for (int ks = 0; ks < 8; ks++) {
            const int kb = ks * 8;
            uint32_t ah[4], bfr[2][4];
            ldsm4(ah, smaddr(qsh + wtokA * FSTR + kb + aoffF));
            ldsm4(bfr[0], smaddr(projT + wmA * FSTR + kb + boffF));
            ldsm4(bfr[1], smaddr(projT + (wmA + 16) * FSTR + kb + boffF));
#pragma unroll
            for (int nj = 0; nj < 4; nj++)
                mma_tf32(pacc[nj], ah, &bfr[nj >> 1][(nj & 1) * 2]);
        }

#pragma unroll
        for (int nj = 0; nj < 4; nj++)
#pragma unroll
            for (int half = 0; half < 2; half++) {
                int tok = wtokA + g + half * 8;
                int m0 = wmA + nj * 8 + 2 * c;
                float p0 = pacc[nj][half * 2 + 0] * INV_SQRT_DH;
                float p1 = pacc[nj][half * 2 + 1] * INV_SQRT_DH;
                *(float2*)&qps[tok * QSTR + m0] = make_float2(
                    tf32r(__cosf(p0) * INV_SQRT_MF), tf32r(__cosf(p1) * INV_SQRT_MF));
                *(float2*)&qps[tok * QSTR + m0 + 128] = make_float2(
                    tf32r(__sinf(p0) * INV_SQRT_MF), tf32r(__sinf(p1) * INV_SQRT_MF));
            }
        __syncthreads();

        // Step B: out[64,64] = q' @ kvT
        float oacc[2][4];
#pragma unroll
        for (int nj = 0; nj < 2; nj++)
#pragma unroll
            for (int r = 0; r < 4; r++) oacc[nj][r] = 0.f;

#pragma unroll
        for (int ks = 0; ks < 32; ks++) {
            const int kb = ks * 8;
            uint32_t af[4], bv2[4];
            ldsm4(af, smaddr(qps + tokB * QSTR + kb + aoffQ));
            ldsm4(bv2, smaddr(kvt + dB * QSTR + kb + boffQ));
#pragma unroll
            for (int nj = 0; nj < 2; nj++)
                mma_tf32(oacc[nj], af, &bv2[nj * 2]);
        }

#pragma unroll
        for (int nj = 0; nj < 2; nj++) {
            int tok = l0 + tokB + g;
            int col = h * DH + dB + nj * 8 + 2 * c;
            *(float2*)(out + (size_t)(b * LL + tok) * DM + col) =
                make_float2(tf32r(oacc[nj][0]), tf32r(oacc[nj][1]));
            *(float2*)(out + (size_t)(b * LL + tok + 8) * DM + col) =
                make_float2(tf32r(oacc[nj][2]), tf32r(oacc[nj][3]));
        }
    }
}

// ---------------------------------------------------------------------------
extern "C" void kernel_launch(void* const* d_in, const int* in_sizes, int n_in,
                              void* d_out, int out_size)
{
    const float* x    = (const float*)d_in[0];
    const float* proj = (const float*)d_in[1];
    const float* Wq   = (const float*)d_in[2];
    const float* bq   = (const float*)d_in[3];
    const float* Wk   = (const float*)d_in[4];
    const float* bk   = (const float*)d_in[5];
    const float* Wv   = (const float*)d_in[6];
    const float* bv   = (const float*)d_in[7];
    const float* Wo   = (const float*)d_in[8];
    const float* bo   = (const float*)d_in[9];
    float* out = (float*)d_out;

    float *q, *k, *v, *att, *wr, *kvp, *kvf;
    cudaGetSymbolAddress((void**)&q,   g_q);
    cudaGetSymbolAddress((void**)&k,   g_k);
    cudaGetSymbolAddress((void**)&v,   g_v);
    cudaGetSymbolAddress((void**)&att, g_att);
    cudaGetSymbolAddress((void**)&wr,  g_wr);
    cudaGetSymbolAddress((void**)&kvp, g_kvp);
    cudaGetSymbolAddress((void**)&kvf, g_kv);

    static cudaStream_t s2 = nullptr;
    static cudaEvent_t evFork = nullptr, evJoin = nullptr;
    static bool init_done = false;
    if (!init_done) {
        cudaFuncSetAttribute(kv_gemm, cudaFuncAttributeMaxDynamicSharedMemorySize, GSMEM);
        cudaFuncSetAttribute(gemm_one, cudaFuncAttributeMaxDynamicSharedMemorySize, GSMEM);
        cudaFuncSetAttribute(feat_kv, cudaFuncAttributeMaxDynamicSharedMemorySize, FEAT_SMEM);
        cudaFuncSetAttribute(attn_mma, cudaFuncAttributeMaxDynamicSharedMemorySize, ATTN_SMEM);
        cudaStreamCreateWithFlags(&s2, cudaStreamNonBlocking);
        cudaEventCreateWithFlags(&evFork, cudaEventDisableTiming);
        cudaEventCreateWithFlags(&evJoin, cudaEventDisableTiming);
        init_done = true;
    }

    const int WN4ALL = DM * DM;
    round_w<<<(WN4ALL + 255) / 256, 256>>>(
        (const float4*)Wq, (const float4*)Wk, (const float4*)Wv, (const float4*)Wo,
        (float4*)wr);

    // fork: Q-projection on s2, concurrent with the K/V + feature chain
    cudaEventRecord(evFork, 0);
    cudaStreamWaitEvent(s2, evFork, 0);
    gemm_one<<<dim3(DM / 128, TT / 128), 256, GSMEM, s2>>>(x, wr + 0 * DM * DM, bq, q);
    cudaEventRecord(evJoin, s2);

    kv_gemm<<<dim3(DM / 128, TT / 128, 2), 256, GSMEM>>>(x, wr, bk, bv, k, v);

    feat_kv<<<dim3(KV_SPLIT, HH, BB), 512, FEAT_SMEM>>>(k, v, proj, kvp);

    const int N4 = BB * HH * TWO_M * DH / 4;
    kv_reduce<<<(N4 + 255) / 256, 256>>>((const float4*)kvp, (float4*)kvf);

    cudaStreamWaitEvent(0, evJoin, 0);

    attn_mma<<<dim3(LL / (64 * ACH), HH, BB), 512, ATTN_SMEM>>>(q, kvf, proj, att);

    gemm_one<<<dim3(DM / 128, TT / 128), 256, GSMEM>>>(att, wr + 3 * DM * DM, bo, out);
}

// round 13
// speedup vs baseline: 1.1906x; 1.0315x over previous
#include <cuda_runtime.h>
#include <math.h>
#include <stdint.h>

#define BB 4
#define LL 4096
#define TT (BB*LL)
#define DM 1024
#define HH 16
#define DH 64
#define MF 128
#define TWO_M 256
#define KV_SPLIT 16
#define LSPLIT (LL/KV_SPLIT)   // 256

#define INV_SQRT_DH 0.125f
#define INV_SQRT_MF 0.08838834764831843f

__device__ float g_q[TT*DM];
__device__ float g_k[TT*DM];
__device__ float g_v[TT*DM];
__device__ float g_att[TT*DM];
__device__ float g_wr[4*DM*DM];
__device__ float g_kvp[(size_t)KV_SPLIT*BB*HH*TWO_M*DH];
__device__ float g_kv[(size_t)BB*HH*TWO_M*DH];

__device__ __forceinline__ float tf32r(float x) {
    uint32_t u;
    asm("cvt.rna.tf32.f32 %0, %1;" : "=r"(u) : "f"(x));
    return __uint_as_float(u);
}

__device__ __forceinline__ void mma_tf32(float* d, const uint32_t* a, const uint32_t* b) {
    asm volatile(
        "mma.sync.aligned.m16n8k8.row.col.f32.tf32.tf32.f32 "
        "{%0,%1,%2,%3}, {%4,%5,%6,%7}, {%8,%9}, {%0,%1,%2,%3};\n"
        : "+f"(d[0]), "+f"(d[1]), "+f"(d[2]), "+f"(d[3])
        : "r"(a[0]), "r"(a[1]), "r"(a[2]), "r"(a[3]), "r"(b[0]), "r"(b[1]));
}

__device__ __forceinline__ uint32_t smaddr(const void* p) {
    return (uint32_t)__cvta_generic_to_shared(p);
}

__device__ __forceinline__ void ldsm4(uint32_t* r, uint32_t a) {
    asm volatile("ldmatrix.sync.aligned.m8n8.x4.shared.b16 {%0,%1,%2,%3}, [%4];"
                 : "=r"(r[0]), "=r"(r[1]), "=r"(r[2]), "=r"(r[3]) : "r"(a));
}

#define AOFF(lane, STR) (((((lane) >> 3) & 1) * 8 + ((lane) & 7)) * (STR) + ((lane) >> 4) * 4)
#define BOFF(lane, STR) ((((lane) >> 4) * 8 + ((lane) & 7)) * (STR) + (((lane) >> 3) & 1) * 4)

// ---------------------------------------------------------------------------
__global__ void round_w(const float4* __restrict__ wq, const float4* __restrict__ wk,
                        const float4* __restrict__ wv, const float4* __restrict__ wo,
                        float4* __restrict__ dst)
{
    const int WN4 = DM * DM / 4;
    int i = blockIdx.x * 256 + threadIdx.x;
    if (i >= 4 * WN4) return;
    int sel = i / WN4, off = i - sel * WN4;
    const float4* src = (sel == 0) ? wq : (sel == 1) ? wk : (sel == 2) ? wv : wo;
    float4 v = src[off];
    v.x = tf32r(v.x); v.y = tf32r(v.y); v.z = tf32r(v.z); v.w = tf32r(v.w);
    dst[i] = v;
}

// ---------------------------------------------------------------------------
// GEMM body: C[128,128 tile] = A[M,1024] * W[N,1024]^T + bias
// ---------------------------------------------------------------------------
#define GS 3
#define GSTR 36
#define GSTAGE (128*GSTR)
#define GSMEM (2*GS*GSTAGE*4)

__device__ __forceinline__ void gemm_body(
    const float* __restrict__ A, const float* __restrict__ W,
    const float* __restrict__ bias, float* __restrict__ C)
{
    extern __shared__ float sg[];
    float* As = sg;
    float* Ws = sg + GS * GSTAGE;

    const int tid = threadIdx.x;
    const int bm = blockIdx.y * 128;
    const int bn = blockIdx.x * 128;
    const int warp = tid >> 5, lane = tid & 31;
    const int wm = (warp & 1) * 64;
    const int wn = (warp >> 1) * 32;
    const int g = lane >> 2, c = lane & 3;
    const int aoff = AOFF(lane, GSTR);
    const int boff = BOFF(lane, GSTR);

    float d[4][4][4];
#pragma unroll
    for (int mt = 0; mt < 4; mt++)
#pragma unroll
        for (int nt = 0; nt < 4; nt++)
#pragma unroll
            for (int r = 0; r < 4; r++) d[mt][nt][r] = 0.f;

    auto issue = [&](int st, int k0) {
#pragma unroll
        for (int j = 0; j < 4; j++) {
            int id = tid + j * 256;
            int row = id >> 3, kq = (id & 7) * 4;
            asm volatile("cp.async.cg.shared.global [%0], [%1], 16;\n"
                         :: "r"(smaddr(&As[st * GSTAGE + row * GSTR + kq])),
                            "l"(A + (size_t)(bm + row) * DM + k0 + kq));
            asm volatile("cp.async.cg.shared.global [%0], [%1], 16;\n"
                         :: "r"(smaddr(&Ws[st * GSTAGE + row * GSTR + kq])),
                            "l"(W + (size_t)(bn + row) * DM + k0 + kq));
        }
    };

    issue(0, 0);  asm volatile("cp.async.commit_group;\n");
    issue(1, 32); asm volatile("cp.async.commit_group;\n");

    const int NIT = DM / 32;
    for (int i = 0; i < NIT; i++) {
        asm volatile("cp.async.wait_group 1;\n");
        __syncthreads();
        if (i + 2 < NIT) issue((i + 2) % GS, (i + 2) * 32);
        asm volatile("cp.async.commit_group;\n");

        const float* Ab = As + (i % GS) * GSTAGE;
        const float* Wb = Ws + (i % GS) * GSTAGE;
#pragma unroll
        for (int ks = 0; ks < 4; ks++) {
            const int kb = ks * 8;
            uint32_t a[4][4], bq2[2][4];
#pragma unroll
            for (int mt = 0; mt < 4; mt++)
                ldsm4(a[mt], smaddr(Ab + (wm + mt * 16) * GSTR + kb + aoff));
            ldsm4(bq2[0], smaddr(Wb + wn * GSTR + kb + boff));
            ldsm4(bq2[1], smaddr(Wb + (wn + 16) * GSTR + kb + boff));
#pragma unroll
            for (int mt = 0; mt < 4; mt++)
#pragma unroll
                for (int nt = 0; nt < 4; nt++)
                    mma_tf32(d[mt][nt], a[mt], &bq2[nt >> 1][(nt & 1) * 2]);
        }
    }

#pragma unroll
    for (int nt = 0; nt < 4; nt++) {
        int col = bn + wn + nt * 8 + 2 * c;
        float b0 = bias[col], b1 = bias[col + 1];
#pragma unroll
        for (int mt = 0; mt < 4; mt++) {
            int row = bm + wm + mt * 16 + g;
            *(float2*)(C + (size_t)row * DM + col) =
                make_float2(d[mt][nt][0] + b0, d[mt][nt][1] + b1);
            *(float2*)(C + (size_t)(row + 8) * DM + col) =
                make_float2(d[mt][nt][2] + b0, d[mt][nt][3] + b1);
        }
    }
}

__global__ __launch_bounds__(256, 2) void kv_gemm(
    const float* __restrict__ A, const float* __restrict__ Wr,
    const float* __restrict__ bk, const float* __restrict__ bv,
    float* __restrict__ k, float* __restrict__ v)
{
    int z = blockIdx.z;   // 0 -> K, 1 -> V
    const float* W = Wr + (size_t)(z + 1) * DM * DM;
    const float* bias = (z == 0) ? bk : bv;
    float* C = (z == 0) ? k : v;
    gemm_body(A, W, bias, C);
}

__global__ __launch_bounds__(256, 2) void gemm_one(
    const float* __restrict__ A, const float* __restrict__ W,
    const float* __restrict__ bias, float* __restrict__ C)
{
    gemm_body(A, W, bias, C);
}

// ---------------------------------------------------------------------------
// feat_kv: per (split,h,b): kv[256,64] = sum_l k'(l)^T v(l). 512 threads.
// 32-token chunks; smem 87.5 KB -> 2 CTAs/SM.
// ---------------------------------------------------------------------------
#define FSTR 68
#define TSTR 36
#define FEAT_SMEM ((128*FSTR + 32*FSTR + 64*TSTR + 256*TSTR) * 4)   // 89600 B

__global__ __launch_bounds__(512, 2) void feat_kv(
    const float* __restrict__ Kmat, const float* __restrict__ Vmat,
    const float* __restrict__ proj, float* __restrict__ kvp)
{
    extern __shared__ float sm[];
    float* projT = sm;                    // [128 m][68]
    float* ksh   = projT + 128 * FSTR;    // [32 tok][68]
    float* vts   = ksh   + 32 * FSTR;     // [64 d][36 tok]
    float* kpt   = vts   + 64 * TSTR;     // [256 m'][36 tok]

    const int split = blockIdx.x, h = blockIdx.y, b = blockIdx.z;
    const int tid = threadIdx.x;
    const int warp = tid >> 5, lane = tid & 31;
    const int g = lane >> 2, c = lane & 3;
    const int aoffF = AOFF(lane, FSTR);
    const int boffF = BOFF(lane, FSTR);
    const int aoffT = AOFF(lane, TSTR);
    const int boffT = BOFF(lane, TSTR);

    for (int it = tid; it < 2048; it += 512) {
        int d = it >> 5;
        int m4 = (it & 31) * 4;
        float4 pv = *(const float4*)(proj + d * MF + m4);
        projT[(m4 + 0) * FSTR + d] = tf32r(pv.x);
        projT[(m4 + 1) * FSTR + d] = tf32r(pv.y);
        projT[(m4 + 2) * FSTR + d] = tf32r(pv.z);
        projT[(m4 + 3) * FSTR + d] = tf32r(pv.w);
    }

    // Step A tiling: 16 warps cover 32 tok x 128 m with 16x16 tiles
    const int wtokA = (warp & 1) * 16, wmA = (warp >> 1) * 16;
    // Step B tiling: 16 warps cover 256 m' x 64 d with 32x32 tiles
    const int mB0 = (warp & 7) * 32, dB0 = (warp >> 3) * 32;
    const int l0 = split * LSPLIT;

    float kvacc[2][4][4];
#pragma unroll
    for (int mi = 0; mi < 2; mi++)
#pragma unroll
        for (int nj = 0; nj < 4; nj++)
#pragma unroll
            for (int r = 0; r < 4; r++) kvacc[mi][nj][r] = 0.f;

    for (int ch = 0; ch < LSPLIT; ch += 32) {
        __syncthreads();
        // load 32-token K chunk + V chunk transposed (512 float4 items)
        {
            int it = tid;
            int t = it >> 4;
            int d4 = (it & 15) * 4;
            size_t row = (size_t)(b * LL + l0 + ch + t) * DM + h * DH + d4;
            float4 kvv = *(const float4*)(Kmat + row);
            *(float4*)&ksh[t * FSTR + d4] = make_float4(
                tf32r(kvv.x), tf32r(kvv.y), tf32r(kvv.z), tf32r(kvv.w));
            float4 vv = *(const float4*)(Vmat + row);
            vts[(d4 + 0) * TSTR + t] = tf32r(vv.x);
            vts[(d4 + 1) * TSTR + t] = tf32r(vv.y);
            vts[(d4 + 2) * TSTR + t] = tf32r(vv.z);
            vts[(d4 + 3) * TSTR + t] = tf32r(vv.w);
        }
        __syncthreads();

        // Step A: P[32,128] = K @ projT
        float pacc[2][4];
#pragma unroll
        for (int nj = 0; nj < 2; nj++)
#pragma unroll
            for (int r = 0; r < 4; r++) pacc[nj][r] = 0.f;

#pragma unroll
        for (int ks = 0; ks < 8; ks++) {
            const int kb = ks * 8;
            uint32_t ah[4], bfr[4];
            ldsm4(ah, smaddr(ksh + wtokA * FSTR + kb + aoffF));
            ldsm4(bfr, smaddr(projT + wmA * FSTR + kb + boffF));
#pragma unroll
            for (int nj = 0; nj < 2; nj++)
                mma_tf32(pacc[nj], ah, &bfr[nj * 2]);
        }

        // features -> kpt[m'][tok] (cos | sin), token-stride 36
#pragma unroll
        for (int nj = 0; nj < 2; nj++)
#pragma unroll
            for (int r = 0; r < 4; r++) {
                int tok = wtokA + g + (r >> 1) * 8;
                int m = wmA + nj * 8 + 2 * c + (r & 1);
                float p = pacc[nj][r] * INV_SQRT_DH;
                kpt[m * TSTR + tok] = tf32r(__cosf(p) * INV_SQRT_MF);
                kpt[(m + 128) * TSTR + tok] = tf32r(__sinf(p) * INV_SQRT_MF);
            }
        __syncthreads();

        // Step B: kv[256,64] += k'T[256,32] @ V[32,64]
#pragma unroll
        for (int ks = 0; ks < 4; ks++) {
            const int kb = ks * 8;
            uint32_t af[2][4], bv2[2][4];
#pragma unroll
            for (int mi = 0; mi < 2; mi++)
                ldsm4(af[mi], smaddr(kpt + (mB0 + mi * 16) * TSTR + kb + aoffT));
#pragma unroll
            for (int nh = 0; nh < 2; nh++)
                ldsm4(bv2[nh], smaddr(vts + (dB0 + nh * 16) * TSTR + kb + boffT));
#pragma unroll
            for (int mi = 0; mi < 2; mi++)
#pragma unroll
                for (int nj = 0; nj < 4; nj++)
                    mma_tf32(kvacc[mi][nj], af[mi], &bv2[nj >> 1][(nj & 1) * 2]);
        }
    }

    float* outp = kvp + ((size_t)split * BB * HH + b * HH + h) * TWO_M * DH;
#pragma unroll
    for (int mi = 0; mi < 2; mi++)
#pragma unroll
        for (int nj = 0; nj < 4; nj++) {
            int m = mB0 + mi * 16 + g;
            int d = dB0 + nj * 8 + 2 * c;
            *(float2*)(outp + m * DH + d) =
                make_float2(kvacc[mi][nj][0], kvacc[mi][nj][1]);
            *(float2*)(outp + (m + 8) * DH + d) =
                make_float2(kvacc[mi][nj][2], kvacc[mi][nj][3]);
        }
}

// ---------------------------------------------------------------------------
__global__ void kv_reduce(const float4* __restrict__ kvp, float4* __restrict__ kv)
{
    const int N4 = BB * HH * TWO_M * DH / 4;
    int i = blockIdx.x * blockDim.x + threadIdx.x;
    if (i >= N4) return;
    float4 s = kvp[i];
#pragma unroll
    for (int sp = 1; sp < KV_SPLIT; sp++) {
        float4 t = kvp[(size_t)sp * N4 + i];
        s.x += t.x; s.y += t.y; s.z += t.z; s.w += t.w;
    }
    kv[i] = s;
}

// ---------------------------------------------------------------------------
// attn: out[tok,64] = q'[tok,256] @ kv[256,64]. 512 threads, ACH=8 chunks.
// ---------------------------------------------------------------------------
#define ACH 8
#define QSTR 260
#define ATTN_SMEM ((128*FSTR + 64*FSTR + 2*64*QSTR) * 4)   // 185344 B

__global__ __launch_bounds__(512) void attn_mma(
    const float* __restrict__ Q, const float* __restrict__ kv,
    const float* __restrict__ proj, float* __restrict__ out)
{
    extern __shared__ float sm[];
    float* projT = sm;                    // [128][68]
    float* qsh   = projT + 128 * FSTR;    // [64][68]
    float* qps   = qsh   + 64 * FSTR;     // [64 tok][260]
    float* kvt   = qps   + 64 * QSTR;     // [64 d][260 m']

    const int h = blockIdx.y, b = blockIdx.z;
    const int tid = threadIdx.x;
    const int warp = tid >> 5, lane = tid & 31;
    const int g = lane >> 2, c = lane & 3;
    const int aoffF = AOFF(lane, FSTR);
    const int boffF = BOFF(lane, FSTR);
    const int aoffQ = AOFF(lane, QSTR);
    const int boffQ = BOFF(lane, QSTR);

    for (int it = tid; it < 2048; it += 512) {
        int d = it >> 5;
        int m4 = (it & 31) * 4;
        float4 pv = *(const float4*)(proj + d * MF + m4);
        projT[(m4 + 0) * FSTR + d] = tf32r(pv.x);
        projT[(m4 + 1) * FSTR + d] = tf32r(pv.y);
        projT[(m4 + 2) * FSTR + d] = tf32r(pv.z);
        projT[(m4 + 3) * FSTR + d] = tf32r(pv.w);
    }
    const float* kvsrc = kv + ((size_t)(b * HH + h)) * TWO_M * DH;
    for (int it = tid; it < 4096; it += 512) {
        int m = it >> 4;
        int d4 = (it & 15) * 4;
        float4 v = *(const float4*)(kvsrc + m * DH + d4);
        kvt[(d4 + 0) * QSTR + m] = tf32r(v.x);
        kvt[(d4 + 1) * QSTR + m] = tf32r(v.y);
        kvt[(d4 + 2) * QSTR + m] = tf32r(v.z);
        kvt[(d4 + 3) * QSTR + m] = tf32r(v.w);
    }

    const int wtokA = (warp & 3) * 16, wmA = (warp >> 2) * 32;
    const int tokB = (warp & 3) * 16, dB = (warp >> 2) * 16;

    for (int cc = 0; cc < ACH; cc++) {
        const int l0 = (blockIdx.x * ACH + cc) * 64;
        __syncthreads();
        for (int it = tid; it < 1024; it += 512) {
            int t = it >> 4;
            int d4 = (it & 15) * 4;
            size_t row = (size_t)(b * LL + l0 + t) * DM + h * DH + d4;
            float4 qv = *(const float4*)(Q + row);
            *(float4*)&qsh[t * FSTR + d4] = make_float4(
                tf32r(qv.x), tf32r(qv.y), tf32r(qv.z), tf32r(qv.w));
        }
        __syncthreads();

        float pacc[4][4];
#pragma unroll
        for (int nj = 0; nj < 4; nj++)
#pragma unroll
            for (int r = 0; r < 4; r++) pacc[nj][r] = 0.f;

#pragma unroll
        for (int ks = 0; ks < 8; ks++) {
            const int kb = ks * 8;
            uint32_t ah[4], bfr[2][4];
            ldsm4(ah, smaddr(qsh + wtokA * FSTR + kb + aoffF));
            ldsm4(bfr[0], smaddr(projT + wmA * FSTR + kb + boffF));
            ldsm4(bfr[1], smaddr(projT + (wmA + 16) * FSTR + kb + boffF));
#pragma unroll
            for (int nj = 0; nj < 4; nj++)
                mma_tf32(pacc[nj], ah, &bfr[nj >> 1][(nj & 1) * 2]);
        }

#pragma unroll
        for (int nj = 0; nj < 4; nj++)
#pragma unroll
            for (int half = 0; half < 2; half++) {
                int tok = wtokA + g + half * 8;
                int m0 = wmA + nj * 8 + 2 * c;
                float p0 = pacc[nj][half * 2 + 0] * INV_SQRT_DH;
                float p1 = pacc[nj][half * 2 + 1] * INV_SQRT_DH;
                *(float2*)&qps[tok * QSTR + m0] = make_float2(
                    tf32r(__cosf(p0) * INV_SQRT_MF), tf32r(__cosf(p1) * INV_SQRT_MF));
                *(float2*)&qps[tok * QSTR + m0 + 128] = make_float2(
                    tf32r(__sinf(p0) * INV_SQRT_MF), tf32r(__sinf(p1) * INV_SQRT_MF));
            }
        __syncthreads();

        float oacc[2][4];
#pragma unroll
        for (int nj = 0; nj < 2; nj++)
#pragma unroll
            for (int r = 0; r < 4; r++) oacc[nj][r] = 0.f;

#pragma unroll
        for (int ks = 0; ks < 32; ks++) {
            const int kb = ks * 8;
            uint32_t af[4], bv2[4];
            ldsm4(af, smaddr(qps + tokB * QSTR + kb + aoffQ));
            ldsm4(bv2, smaddr(kvt + dB * QSTR + kb + boffQ));
#pragma unroll
            for (int nj = 0; nj < 2; nj++)
                mma_tf32(oacc[nj], af, &bv2[nj * 2]);
        }

#pragma unroll
        for (int nj = 0; nj < 2; nj++) {
            int tok = l0 + tokB + g;
            int col = h * DH + dB + nj * 8 + 2 * c;
            *(float2*)(out + (size_t)(b * LL + tok) * DM + col) =
                make_float2(tf32r(oacc[nj][0]), tf32r(oacc[nj][1]));
            *(float2*)(out + (size_t)(b * LL + tok + 8) * DM + col) =
                make_float2(tf32r(oacc[nj][2]), tf32r(oacc[nj][3]));
        }
    }
}

// ---------------------------------------------------------------------------
extern "C" void kernel_launch(void* const* d_in, const int* in_sizes, int n_in,
                              void* d_out, int out_size)
{
    const float* x    = (const float*)d_in[0];
    const float* proj = (const float*)d_in[1];
    const float* Wq   = (const float*)d_in[2];
    const float* bq   = (const float*)d_in[3];
    const float* Wk   = (const float*)d_in[4];
    const float* bk   = (const float*)d_in[5];
    const float* Wv   = (const float*)d_in[6];
    const float* bv   = (const float*)d_in[7];
    const float* Wo   = (const float*)d_in[8];
    const float* bo   = (const float*)d_in[9];
    float* out = (float*)d_out;

    float *q, *k, *v, *att, *wr, *kvp, *kvf;
    cudaGetSymbolAddress((void**)&q,   g_q);
    cudaGetSymbolAddress((void**)&k,   g_k);
    cudaGetSymbolAddress((void**)&v,   g_v);
    cudaGetSymbolAddress((void**)&att, g_att);
    cudaGetSymbolAddress((void**)&wr,  g_wr);
    cudaGetSymbolAddress((void**)&kvp, g_kvp);
    cudaGetSymbolAddress((void**)&kvf, g_kv);

    static cudaStream_t s2 = nullptr;
    static cudaEvent_t evFork = nullptr, evJoin = nullptr;
    static bool init_done = false;
    if (!init_done) {
        cudaFuncSetAttribute(kv_gemm, cudaFuncAttributeMaxDynamicSharedMemorySize, GSMEM);
        cudaFuncSetAttribute(gemm_one, cudaFuncAttributeMaxDynamicSharedMemorySize, GSMEM);
        cudaFuncSetAttribute(feat_kv, cudaFuncAttributeMaxDynamicSharedMemorySize, FEAT_SMEM);
        cudaFuncSetAttribute(attn_mma, cudaFuncAttributeMaxDynamicSharedMemorySize, ATTN_SMEM);
        cudaStreamCreateWithFlags(&s2, cudaStreamNonBlocking);
        cudaEventCreateWithFlags(&evFork, cudaEventDisableTiming);
        cudaEventCreateWithFlags(&evJoin, cudaEventDisableTiming);
        init_done = true;
    }

    const int WN4ALL = DM * DM;
    round_w<<<(WN4ALL + 255) / 256, 256>>>(
        (const float4*)Wq, (const float4*)Wk, (const float4*)Wv, (const float4*)Wo,
        (float4*)wr);

    // fork: Q-projection on s2, concurrent with the K/V + feature chain
    cudaEventRecord(evFork, 0);
    cudaStreamWaitEvent(s2, evFork, 0);
    gemm_one<<<dim3(DM / 128, TT / 128), 256, GSMEM, s2>>>(x, wr + 0 * DM * DM, bq, q);
    cudaEventRecord(evJoin, s2);

    kv_gemm<<<dim3(DM / 128, TT / 128, 2), 256, GSMEM>>>(x, wr, bk, bv, k, v);

    feat_kv<<<dim3(KV_SPLIT, HH, BB), 512, FEAT_SMEM>>>(k, v, proj, kvp);

    const int N4 = BB * HH * TWO_M * DH / 4;
    kv_reduce<<<(N4 + 255) / 256, 256>>>((const float4*)kvp, (float4*)kvf);

    cudaStreamWaitEvent(0, evJoin, 0);

    attn_mma<<<dim3(LL / (64 * ACH), HH, BB), 512, ATTN_SMEM>>>(q, kvf, proj, att);

    gemm_one<<<dim3(DM / 128, TT / 128), 256, GSMEM>>>(att, wr + 3 * DM * DM, bo, out);
}